// round 16
// baseline (speedup 1.0000x reference)
#include <cuda_runtime.h>
#include <math.h>

#define B_  32
#define P_  196
#define D_  512
#define H_  8
#define U_  4
#define C_  500

#define KNOWN_ELEMS (16000LL * 11 * 512)   // 90,112,000
#define UNK_ELEMS   (32LL * 7 * 512)       // 114,688
#define ST_ELEMS    (32LL * 8 * 512)       // 131,072

// Scratch (device-global, allocation-free)
__device__ float g_pd[B_ * D_];              // projected_domain  [32,512]
__device__ float g_psem[B_ * H_ * D_];       // projected_sem     [32,8,512]

// ---------------------------------------------------------------------------
// K1: fully fused attention pooling.
// Grid (b=32, dg=4), block 256 (8 warps).
// Phase 1: all 8 warps compute scores for ALL p of this b (4x duplicated
//          across dg blocks -- cheap, keeps patch[b] slab L2-hot).
// Phase 2: softmax in smem (warp per head).
// Phase 3: pooling for this block's 128-d slice; threads split p in halves
//          (pz), partials combined through smem; writes semantic_tokens.
// ---------------------------------------------------------------------------
__global__ __launch_bounds__(256) void k_attn(
    const float* __restrict__ patch,   // [B,P,D]
    const float* __restrict__ qv,      // [H,D]
    float* __restrict__ st_out)        // [B,H,D]
{
    __shared__ float4 q_s4[H_ * 128];  // 16 KB
    __shared__ float  sc[P_][H_];      // 6.3 KB
    __shared__ float  part[H_][128];   // 4 KB

    const int b    = blockIdx.x;
    const int dg   = blockIdx.y;       // 0..3 -> d slice of 128
    const int tid  = threadIdx.x;
    const int warp = tid >> 5;
    const int lane = tid & 31;

    for (int i = tid; i < H_ * 128; i += 256) q_s4[i] = ((const float4*)qv)[i];
    __syncthreads();

    const float4* pb4 = (const float4*)(patch + (size_t)b * P_ * D_);

    // Phase 1: scores for all p (8 warps stride rows)
    for (int p = warp; p < P_; p += 8) {
        const float4* r4 = pb4 + (size_t)p * 128;
        float4 v[4];
        #pragma unroll
        for (int i2 = 0; i2 < 4; i2++) v[i2] = r4[i2 * 32 + lane];

        float acc[H_];
        #pragma unroll
        for (int h = 0; h < H_; h++) acc[h] = 0.f;
        #pragma unroll
        for (int i2 = 0; i2 < 4; i2++) {
            #pragma unroll
            for (int h = 0; h < H_; h++) {
                float4 q = q_s4[h * 128 + i2 * 32 + lane];
                acc[h] = fmaf(v[i2].x, q.x, acc[h]);
                acc[h] = fmaf(v[i2].y, q.y, acc[h]);
                acc[h] = fmaf(v[i2].z, q.z, acc[h]);
                acc[h] = fmaf(v[i2].w, q.w, acc[h]);
            }
        }
        #pragma unroll
        for (int h = 0; h < H_; h++) {
            float a = acc[h];
            #pragma unroll
            for (int o = 16; o > 0; o >>= 1) a += __shfl_xor_sync(0xFFFFFFFFu, a, o);
            acc[h] = a;
        }
        if (lane == 0) {
            #pragma unroll
            for (int h = 0; h < H_; h++) sc[p][h] = acc[h];
        }
    }
    __syncthreads();

    // Phase 2: softmax over p, warp per head
    {
        const int h = warp;
        float m = -INFINITY;
        for (int p = lane; p < P_; p += 32) m = fmaxf(m, sc[p][h]);
        #pragma unroll
        for (int o = 16; o > 0; o >>= 1) m = fmaxf(m, __shfl_xor_sync(0xFFFFFFFFu, m, o));
        float s = 0.f;
        for (int p = lane; p < P_; p += 32) {
            float e = __expf(sc[p][h] - m);
            sc[p][h] = e;
            s += e;
        }
        #pragma unroll
        for (int o = 16; o > 0; o >>= 1) s += __shfl_xor_sync(0xFFFFFFFFu, s, o);
        float inv = 1.f / s;
        for (int p = lane; p < P_; p += 32) sc[p][h] *= inv;
    }
    __syncthreads();

    // Phase 3: pooling. thread = (pz, d_loc); 98 p-rows each, unroll 8.
    const int d_loc = tid & 127;
    const int pz    = tid >> 7;        // 0/1
    const int d     = dg * 128 + d_loc;
    const float* pb = patch + (size_t)b * P_ * D_;

    float acc[H_];
    #pragma unroll
    for (int h = 0; h < H_; h++) acc[h] = 0.f;

    int p = pz * 98;
    for (int bb = 0; bb < 12; bb++, p += 8) {
        float v[8];
        #pragma unroll
        for (int u = 0; u < 8; u++) v[u] = pb[(size_t)(p + u) * D_ + d];
        #pragma unroll
        for (int u = 0; u < 8; u++) {
            #pragma unroll
            for (int h = 0; h < H_; h++) acc[h] = fmaf(sc[p + u][h], v[u], acc[h]);
        }
    }
    {
        float v0 = pb[(size_t)p * D_ + d];
        float v1 = pb[(size_t)(p + 1) * D_ + d];
        #pragma unroll
        for (int h = 0; h < H_; h++) {
            acc[h] = fmaf(sc[p][h], v0, acc[h]);
            acc[h] = fmaf(sc[p + 1][h], v1, acc[h]);
        }
    }
    if (pz == 1) {
        #pragma unroll
        for (int h = 0; h < H_; h++) part[h][d_loc] = acc[h];
    }
    __syncthreads();
    if (pz == 0) {
        #pragma unroll
        for (int h = 0; h < H_; h++)
            st_out[((size_t)b * H_ + h) * D_ + d] = acc[h] + part[h][d_loc];
    }
}

// ---------------------------------------------------------------------------
// K3: fused sem + dom projections, 2-e-per-warp.
// hh in [0,8): psem[b,hh,e] = st[b,hh,:] . sem_W[hh,e,:] + sem_b[hh,e]
// hh == 8  : pd[b,e]       = gf[b,:]    . dom_W[e,:]     + dom_b[e]
// Grid (eg=32, hh=9, bg=4) = 1152 blocks; block 256 (8 warps).
// ---------------------------------------------------------------------------
__global__ __launch_bounds__(256) void k_semdom(
    const float* __restrict__ st,      // [B,H,D] (output region, from k_attn)
    const float* __restrict__ semW,    // [H,D,D]
    const float* __restrict__ semb,    // [H,D]
    const float* __restrict__ gf,      // [B,D]
    const float* __restrict__ domW,    // [D,D]
    const float* __restrict__ domb)    // [D]
{
    __shared__ float4 st4[8][128];     // 16 KB

    const int eg  = blockIdx.x;        // 0..31 -> 16 e each
    const int hh  = blockIdx.y;        // 0..8 (8 == domain)
    const int bg  = blockIdx.z;        // 0..3 -> 8 b each
    const int tid = threadIdx.x;
    const int warp = tid >> 5;
    const int lane = tid & 31;

    const bool is_dom = (hh == H_);
    const float4* src4 = is_dom ? (const float4*)gf : (const float4*)st;
    const float4* W4   = is_dom ? (const float4*)domW
                                : (const float4*)semW + (size_t)hh * D_ * 128;
    const float* bias_p = is_dom ? domb : (semb + hh * D_);
    float* outp = is_dom ? g_pd : g_psem;

    for (int i = tid; i < 8 * 128; i += 256) {
        int b_loc = i >> 7, d4 = i & 127;
        int b = bg * 8 + b_loc;
        size_t off = is_dom ? ((size_t)b * 128 + d4)
                            : (((size_t)b * H_ + hh) * 128 + d4);
        st4[b_loc][d4] = src4[off];
    }
    __syncthreads();

    const int e0 = eg * 16 + warp * 2;
    const float4* wrow0 = W4 + (size_t)e0 * 128;
    const float4* wrow1 = W4 + (size_t)(e0 + 1) * 128;

    float4 wv0[4], wv1[4];
    #pragma unroll
    for (int it = 0; it < 4; it++) {
        wv0[it] = __ldg(wrow0 + it * 32 + lane);
        wv1[it] = __ldg(wrow1 + it * 32 + lane);
    }

    float acc0[8], acc1[8];
    #pragma unroll
    for (int j = 0; j < 8; j++) { acc0[j] = 0.f; acc1[j] = 0.f; }

    #pragma unroll
    for (int it = 0; it < 4; it++) {
        #pragma unroll
        for (int j = 0; j < 8; j++) {
            float4 s = st4[j][it * 32 + lane];
            acc0[j] = fmaf(wv0[it].x, s.x, acc0[j]);
            acc0[j] = fmaf(wv0[it].y, s.y, acc0[j]);
            acc0[j] = fmaf(wv0[it].z, s.z, acc0[j]);
            acc0[j] = fmaf(wv0[it].w, s.w, acc0[j]);
            acc1[j] = fmaf(wv1[it].x, s.x, acc1[j]);
            acc1[j] = fmaf(wv1[it].y, s.y, acc1[j]);
            acc1[j] = fmaf(wv1[it].z, s.z, acc1[j]);
            acc1[j] = fmaf(wv1[it].w, s.w, acc1[j]);
        }
    }
    #pragma unroll
    for (int j = 0; j < 8; j++) {
        float a0 = acc0[j], a1 = acc1[j];
        #pragma unroll
        for (int o = 16; o > 0; o >>= 1) {
            a0 += __shfl_xor_sync(0xFFFFFFFFu, a0, o);
            a1 += __shfl_xor_sync(0xFFFFFFFFu, a1, o);
        }
        acc0[j] = a0; acc1[j] = a1;
    }
    if (lane == 0) {
        const float bias0 = bias_p[e0];
        const float bias1 = bias_p[e0 + 1];
        #pragma unroll
        for (int j = 0; j < 8; j++) {
            const int b = bg * 8 + j;
            size_t base = is_dom ? ((size_t)b * D_)
                                 : (((size_t)b * H_ + hh) * D_);
            outp[base + e0]     = acc0[j] + bias0;
            outp[base + e0 + 1] = acc1[j] + bias1;
        }
    }
}

// ---------------------------------------------------------------------------
// K4: known_prompts writer, warp-per-token + fused unknown_prompts.
// Grid (cg=21, b=32), block 352 (11 warps). cg<20: warp w owns token w of
// 25 prompt rows. Warps 1..9 (pd/psem) hold their 2KB row in 4 registers and
// only issue STG.128 in the c-loop; warps 0/10 stream prefix/suffix (L2-hot).
// No smem, no syncthreads, no predication, no divergence.
// cg==20: unknown_prompts [B,7,D].
// ---------------------------------------------------------------------------
__global__ __launch_bounds__(352) void k_known(
    const float* __restrict__ kpre,    // [C,1,D]
    const float* __restrict__ ksuf,    // [C,1,D]
    const float* __restrict__ upre,    // [1,D]
    const float* __restrict__ usuf,    // [1,D]
    const float* __restrict__ ust,     // [U,D]
    float* __restrict__ out,           // known region  [B*C, 11, D]
    float* __restrict__ unk_out)       // unknown region [B, 7, D]
{
    const int cg  = blockIdx.x;        // 0..20
    const int b   = blockIdx.y;
    const int tid = threadIdx.x;
    const int warp = tid >> 5;
    const int lane = tid & 31;

    if (cg == 20) {
        // unknown_prompts for this b: 896 float4
        float4* out4 = (float4*)unk_out + (size_t)b * 896;
        const float4* upre4 = (const float4*)upre;
        const float4* usuf4 = (const float4*)usuf;
        const float4* ust4  = (const float4*)ust;
        const float4* pd4   = (const float4*)(g_pd + (size_t)b * D_);
        for (int i = tid; i < 896; i += 352) {
            int t = i >> 7, d4 = i & 127;
            float4 v;
            if (t == 0)      v = upre4[d4];
            else if (t == 1) v = pd4[d4];
            else if (t == 6) v = usuf4[d4];
            else             v = ust4[(t - 2) * 128 + d4];
            out4[i] = v;
        }
        return;
    }

    const int t  = warp;               // token 0..10
    const int c0 = cg * 25;

    // middle tokens: load row once into registers
    float4 mid[4];
    if (t >= 1 && t <= 9) {
        const float4* src = (t == 1)
            ? (const float4*)(g_pd + (size_t)b * D_)
            : (const float4*)(g_psem + ((size_t)b * H_ + (t - 2)) * D_);
        #pragma unroll
        for (int i = 0; i < 4; i++) mid[i] = src[i * 32 + lane];
    }

    // base of this warp's token within the first row this block writes
    float4* wout = (float4*)out + ((size_t)b * C_ + c0) * 1408 + t * 128;
    const float4* pre4 = (const float4*)kpre + (size_t)c0 * 128;
    const float4* suf4 = (const float4*)ksuf + (size_t)c0 * 128;

    if (t == 0) {
        for (int cc = 0; cc < 25; cc++) {
            float4* row = wout + (size_t)cc * 1408;
            float4 v[4];
            #pragma unroll
            for (int i = 0; i < 4; i++) v[i] = __ldg(pre4 + cc * 128 + i * 32 + lane);
            #pragma unroll
            for (int i = 0; i < 4; i++) row[i * 32 + lane] = v[i];
        }
    } else if (t == 10) {
        for (int cc = 0; cc < 25; cc++) {
            float4* row = wout + (size_t)cc * 1408;
            float4 v[4];
            #pragma unroll
            for (int i = 0; i < 4; i++) v[i] = __ldg(suf4 + cc * 128 + i * 32 + lane);
            #pragma unroll
            for (int i = 0; i < 4; i++) row[i * 32 + lane] = v[i];
        }
    } else {
        for (int cc = 0; cc < 25; cc++) {
            float4* row = wout + (size_t)cc * 1408;
            #pragma unroll
            for (int i = 0; i < 4; i++) row[i * 32 + lane] = mid[i];
        }
    }
}

// ---------------------------------------------------------------------------
extern "C" void kernel_launch(void* const* d_in, const int* in_sizes, int n_in,
                              void* d_out, int out_size)
{
    const float* patch = (const float*)d_in[0];   // [B,P,D]
    const float* gf    = (const float*)d_in[1];   // [B,D]
    const float* qv    = (const float*)d_in[2];   // [H,D]
    const float* domW  = (const float*)d_in[3];   // [D,D]
    const float* domb  = (const float*)d_in[4];   // [D]
    const float* semW  = (const float*)d_in[5];   // [H,D,D]
    const float* semb  = (const float*)d_in[6];   // [H,D]
    const float* ust   = (const float*)d_in[7];   // [U,D]
    const float* kpre  = (const float*)d_in[8];   // [C,1,D]
    const float* ksuf  = (const float*)d_in[9];   // [C,1,D]
    const float* upre  = (const float*)d_in[10];  // [1,D]
    const float* usuf  = (const float*)d_in[11];  // [1,D]

    float* out     = (float*)d_out;
    float* unk_out = out + KNOWN_ELEMS;
    float* st_out  = out + KNOWN_ELEMS + UNK_ELEMS;

    dim3 g1(B_, 4);
    k_attn<<<g1, 256>>>(patch, qv, st_out);
    dim3 g3(32, 9, 4);
    k_semdom<<<g3, 256>>>(st_out, semW, semb, gf, domW, domb);
    dim3 g4(21, 32);
    k_known<<<g4, 352>>>(kpre, ksuf, upre, usuf, ust, out, unk_out);
}